// round 7
// baseline (speedup 1.0000x reference)
#include <cuda_runtime.h>

#define KDIM   256
#define NF     64
#define N1R    8192
#define KH     5
#define BM     32
#define BK     32
#define NSPLIT 4
#define KSLICE (KDIM / NSPLIT)   // 64
#define NRT    (N1R / BM)        // 256 row tiles

// split-K partial sums: [NSPLIT][8192][64] = 8.4 MB (allocation-free scratch)
__device__ float g_part[NSPLIT * N1R * NF];
// per-row-tile arrival counters; zero-initialized at load, self-resetting per call
__device__ int   g_cnt[NRT];

// ---------------------------------------------------------------------------
// Fused split-K GEMM + in-kernel reduction.
// out = G @ x @ W + 5*bias; G rows are 5 ones at qq[5i..5i+4]
// (floor(softmax(v)/1000) == 0 identically, so e == G exactly.)
// Grid (256 row-tiles x 4 K-splits) = 1024 CTAs -> 7 CTAs/SM, 28 warps/SM.
// Each split writes its partial; the LAST split CTA per row-tile re-reads all
// 4 partials in fixed split order (bitwise-deterministic sum), adds 5*bias,
// and stores the output. Saves the ~5us separate reduce launch (R6 ncu).
// ---------------------------------------------------------------------------
__global__ __launch_bounds__(128, 7) void gemm_fused_kernel(
        const float* __restrict__ x,
        const int*   __restrict__ qq,
        const float* __restrict__ w,
        const float* __restrict__ bias,
        float*       __restrict__ out) {
    __shared__ float sst[BK][36];      // transposed s tile [k][row]
    __shared__ float ws[BK][NF];       // w tile
    __shared__ int   qs[BM * KH];
    __shared__ int   is_last;

    const int tid = threadIdx.x;
    const int rt  = blockIdx.x;        // row tile 0..255
    const int r0  = rt * BM;
    const int ks  = blockIdx.y * KSLICE;
    const int rg  = tid >> 4;          // 0..7  -> rows rg*4..rg*4+3
    const int cg  = tid & 15;          // 0..15 -> cols cg*4..cg*4+3

    for (int t = tid; t < BM * KH; t += 128) qs[t] = qq[r0 * KH + t];
    __syncthreads();

    const float4* x4 = (const float4*)x;   // x row stride = 64 float4
    const float4* w4 = (const float4*)w;   // w row stride = 16 float4

    float acc[4][4] = {};

    #pragma unroll
    for (int c = 0; c < KSLICE / BK; c++) {
        const int kc = ks + c * BK;

        // w tile [32 x 64]: 512 float4, 4 per thread
        #pragma unroll
        for (int j = 0; j < 4; j++) {
            int idx = tid + j * 128;             // 0..511
            int kk = idx >> 4, c4 = idx & 15;
            *(float4*)&ws[kk][c4 * 4] = w4[(size_t)(kc + kk) * 16 + c4];
        }

        // gather-sum s tile [32 rows x 32 k], stored transposed
        #pragma unroll
        for (int j = 0; j < 2; j++) {
            int idx = tid + j * 128;             // 0..255
            int row = idx >> 3, c4 = idx & 7;
            const float4* xp = x4 + (kc >> 2) + c4;
            const int* q = qs + row * KH;
            float4 a0 = xp[(size_t)q[0] * 64];
            float4 a1 = xp[(size_t)q[1] * 64];
            float4 a2 = xp[(size_t)q[2] * 64];
            float4 a3 = xp[(size_t)q[3] * 64];
            float4 a4 = xp[(size_t)q[4] * 64];
            sst[c4 * 4 + 0][row] = a0.x + a1.x + a2.x + a3.x + a4.x;
            sst[c4 * 4 + 1][row] = a0.y + a1.y + a2.y + a3.y + a4.y;
            sst[c4 * 4 + 2][row] = a0.z + a1.z + a2.z + a3.z + a4.z;
            sst[c4 * 4 + 3][row] = a0.w + a1.w + a2.w + a3.w + a4.w;
        }
        __syncthreads();

        #pragma unroll
        for (int kk = 0; kk < BK; kk++) {
            float4 sv = *(const float4*)&sst[kk][rg * 4];
            float4 wv = *(const float4*)&ws[kk][cg * 4];
            acc[0][0] += sv.x * wv.x; acc[0][1] += sv.x * wv.y;
            acc[0][2] += sv.x * wv.z; acc[0][3] += sv.x * wv.w;
            acc[1][0] += sv.y * wv.x; acc[1][1] += sv.y * wv.y;
            acc[1][2] += sv.y * wv.z; acc[1][3] += sv.y * wv.w;
            acc[2][0] += sv.z * wv.x; acc[2][1] += sv.z * wv.y;
            acc[2][2] += sv.z * wv.z; acc[2][3] += sv.z * wv.w;
            acc[3][0] += sv.w * wv.x; acc[3][1] += sv.w * wv.y;
            acc[3][2] += sv.w * wv.z; acc[3][3] += sv.w * wv.w;
        }
        __syncthreads();
    }

    // ---- publish this split's partial ----
    float4* p = (float4*)(g_part + (size_t)blockIdx.y * (N1R * NF));
    #pragma unroll
    for (int m = 0; m < 4; m++) {
        int row = r0 + rg * 4 + m;
        p[(size_t)row * 16 + cg] =
            make_float4(acc[m][0], acc[m][1], acc[m][2], acc[m][3]);
    }
    __threadfence();                    // make partial visible before arrival

    if (tid == 0) {
        int old = atomicAdd(&g_cnt[rt], 1);
        is_last = (old == NSPLIT - 1);
        if (is_last) g_cnt[rt] = 0;     // self-reset: graph-replay safe
    }
    __syncthreads();

    // ---- last CTA of this row-tile reduces all 4 partials (fixed order) ----
    if (is_last) {
        const float4* pp = (const float4*)g_part;
        float4 bv = ((const float4*)bias)[cg];
        float4* out4 = (float4*)out;
        #pragma unroll
        for (int m = 0; m < 4; m++) {
            size_t idx = (size_t)(r0 + rg * 4 + m) * 16 + cg;
            float4 s0 = pp[idx];
            float4 s1 = pp[idx + (size_t)1 * N1R * 16];
            float4 s2 = pp[idx + (size_t)2 * N1R * 16];
            float4 s3 = pp[idx + (size_t)3 * N1R * 16];
            float4 o;
            o.x = s0.x + s1.x + s2.x + s3.x + 5.0f * bv.x;
            o.y = s0.y + s1.y + s2.y + s3.y + 5.0f * bv.y;
            o.z = s0.z + s1.z + s2.z + s3.z + 5.0f * bv.z;
            o.w = s0.w + s1.w + s2.w + s3.w + 5.0f * bv.w;
            out4[idx] = o;
        }
    }
}

// ---------------------------------------------------------------------------
// Inputs (metadata order):
//   0: x [10000,256] f32, 1: G (unused), 2: weight [256,64] f32,
//   3: a (unused — attention branch identically zero), 4: bias [64] f32,
//   5: qq [40960] i32, 6: rows (unused)
// output: [8192,64] f32
// ---------------------------------------------------------------------------
extern "C" void kernel_launch(void* const* d_in, const int* in_sizes, int n_in,
                              void* d_out, int out_size) {
    const float* x    = (const float*)d_in[0];
    const float* w    = (const float*)d_in[2];
    const float* bias = (const float*)d_in[4];
    const int*   qq   = (const int*)d_in[5];
    float*       out  = (float*)d_out;

    dim3 grid(NRT, NSPLIT);
    gemm_fused_kernel<<<grid, 128>>>(x, qq, w, bias, out);
}

// round 8
// speedup vs baseline: 1.0947x; 1.0947x over previous
#include <cuda_runtime.h>

#define KDIM   256
#define NF     64
#define N1R    8192
#define KH     5
#define BM     32
#define BK     32
#define NSPLIT 4
#define KSLICE (KDIM / NSPLIT)   // 64
#define NRT    (N1R / BM)        // 256 row tiles

// split-K partial sums: [NSPLIT][8192][64] = 8.4 MB (allocation-free scratch)
__device__ float g_part[NSPLIT * N1R * NF];
// per-row-tile arrival counters; zero-initialized at load, self-resetting per call
__device__ int   g_cnt[NRT];

// ---------------------------------------------------------------------------
// Fused split-K GEMM + in-kernel reduction, WITHOUT any L1-flushing fence.
// out = G @ x @ W + 5*bias; G rows are 5 ones at qq[5i..5i+4]
// (floor(softmax(v)/1000) == 0 identically, so e == G exactly.)
//
// R7 lesson: __threadfence() (gpu scope) makes ptxas emit CCTL.IVALL -> 1024
// full L1D invalidates, disrupting the L1TEX pipeline all LDS/gather traffic
// uses (~5.5us). Here ordering is done by:
//   - arrival = atom.release.gpu (orders partial STGs to L2, no invalidate)
//   - last-CTA partial reads = ld.global.cg (L2-only; L2 is coherence point,
//     so no acquire/CCTL needed and no stale-L1 hazard)
// ---------------------------------------------------------------------------
__global__ __launch_bounds__(128, 7) void gemm_fused_kernel(
        const float* __restrict__ x,
        const int*   __restrict__ qq,
        const float* __restrict__ w,
        const float* __restrict__ bias,
        float*       __restrict__ out) {
    __shared__ float sst[BK][36];      // transposed s tile [k][row]
    __shared__ float ws[BK][NF];       // w tile
    __shared__ int   qs[BM * KH];
    __shared__ int   is_last;

    const int tid = threadIdx.x;
    const int rt  = blockIdx.x;        // row tile 0..255
    const int r0  = rt * BM;
    const int ks  = blockIdx.y * KSLICE;
    const int rg  = tid >> 4;          // 0..7  -> rows rg*4..rg*4+3
    const int cg  = tid & 15;          // 0..15 -> cols cg*4..cg*4+3

    for (int t = tid; t < BM * KH; t += 128) qs[t] = qq[r0 * KH + t];
    __syncthreads();

    const float4* x4 = (const float4*)x;   // x row stride = 64 float4
    const float4* w4 = (const float4*)w;   // w row stride = 16 float4

    float acc[4][4] = {};

    #pragma unroll
    for (int c = 0; c < KSLICE / BK; c++) {
        const int kc = ks + c * BK;

        // w tile [32 x 64]: 512 float4, 4 per thread
        #pragma unroll
        for (int j = 0; j < 4; j++) {
            int idx = tid + j * 128;             // 0..511
            int kk = idx >> 4, c4 = idx & 15;
            *(float4*)&ws[kk][c4 * 4] = w4[(size_t)(kc + kk) * 16 + c4];
        }

        // gather-sum s tile [32 rows x 32 k], stored transposed
        #pragma unroll
        for (int j = 0; j < 2; j++) {
            int idx = tid + j * 128;             // 0..255
            int row = idx >> 3, c4 = idx & 7;
            const float4* xp = x4 + (kc >> 2) + c4;
            const int* q = qs + row * KH;
            float4 a0 = xp[(size_t)q[0] * 64];
            float4 a1 = xp[(size_t)q[1] * 64];
            float4 a2 = xp[(size_t)q[2] * 64];
            float4 a3 = xp[(size_t)q[3] * 64];
            float4 a4 = xp[(size_t)q[4] * 64];
            sst[c4 * 4 + 0][row] = a0.x + a1.x + a2.x + a3.x + a4.x;
            sst[c4 * 4 + 1][row] = a0.y + a1.y + a2.y + a3.y + a4.y;
            sst[c4 * 4 + 2][row] = a0.z + a1.z + a2.z + a3.z + a4.z;
            sst[c4 * 4 + 3][row] = a0.w + a1.w + a2.w + a3.w + a4.w;
        }
        __syncthreads();

        #pragma unroll
        for (int kk = 0; kk < BK; kk++) {
            float4 sv = *(const float4*)&sst[kk][rg * 4];
            float4 wv = *(const float4*)&ws[kk][cg * 4];
            acc[0][0] += sv.x * wv.x; acc[0][1] += sv.x * wv.y;
            acc[0][2] += sv.x * wv.z; acc[0][3] += sv.x * wv.w;
            acc[1][0] += sv.y * wv.x; acc[1][1] += sv.y * wv.y;
            acc[1][2] += sv.y * wv.z; acc[1][3] += sv.y * wv.w;
            acc[2][0] += sv.z * wv.x; acc[2][1] += sv.z * wv.y;
            acc[2][2] += sv.z * wv.z; acc[2][3] += sv.z * wv.w;
            acc[3][0] += sv.w * wv.x; acc[3][1] += sv.w * wv.y;
            acc[3][2] += sv.w * wv.z; acc[3][3] += sv.w * wv.w;
        }
        __syncthreads();
    }

    // ---- publish this split's partial ----
    float4* p = (float4*)(g_part + (size_t)blockIdx.y * (N1R * NF));
    #pragma unroll
    for (int m = 0; m < 4; m++) {
        int row = r0 + rg * 4 + m;
        p[(size_t)row * 16 + cg] =
            make_float4(acc[m][0], acc[m][1], acc[m][2], acc[m][3]);
    }

    if (tid == 0) {
        // release-atomic: orders the STGs above to L2 before the arrival,
        // with NO CCTL.IVALL (that's acquire-side).
        int old;
        asm volatile("atom.release.gpu.global.add.s32 %0, [%1], %2;"
                     : "=r"(old) : "l"(&g_cnt[rt]), "r"(1) : "memory");
        is_last = (old == NSPLIT - 1);
        if (is_last) g_cnt[rt] = 0;     // self-reset: graph-replay safe
    }
    __syncthreads();

    // ---- last CTA of this row-tile reduces all 4 partials (fixed order) ----
    if (is_last) {
        const float4* pp = (const float4*)g_part;
        float4 bv = ((const float4*)bias)[cg];
        float4* out4 = (float4*)out;
        #pragma unroll
        for (int m = 0; m < 4; m++) {
            size_t idx = (size_t)(r0 + rg * 4 + m) * 16 + cg;
            float4 s0 = __ldcg(pp + idx);                           // L2-only
            float4 s1 = __ldcg(pp + idx + (size_t)1 * N1R * 16);
            float4 s2 = __ldcg(pp + idx + (size_t)2 * N1R * 16);
            float4 s3 = __ldcg(pp + idx + (size_t)3 * N1R * 16);
            float4 o;
            o.x = s0.x + s1.x + s2.x + s3.x + 5.0f * bv.x;
            o.y = s0.y + s1.y + s2.y + s3.y + 5.0f * bv.y;
            o.z = s0.z + s1.z + s2.z + s3.z + 5.0f * bv.z;
            o.w = s0.w + s1.w + s2.w + s3.w + 5.0f * bv.w;
            out4[idx] = o;
        }
    }
}

// ---------------------------------------------------------------------------
// Inputs (metadata order):
//   0: x [10000,256] f32, 1: G (unused), 2: weight [256,64] f32,
//   3: a (unused — attention branch identically zero), 4: bias [64] f32,
//   5: qq [40960] i32, 6: rows (unused)
// output: [8192,64] f32
// ---------------------------------------------------------------------------
extern "C" void kernel_launch(void* const* d_in, const int* in_sizes, int n_in,
                              void* d_out, int out_size) {
    const float* x    = (const float*)d_in[0];
    const float* w    = (const float*)d_in[2];
    const float* bias = (const float*)d_in[4];
    const int*   qq   = (const int*)d_in[5];
    float*       out  = (float*)d_out;

    dim3 grid(NRT, NSPLIT);
    gemm_fused_kernel<<<grid, 128>>>(x, qq, w, bias, out);
}